// round 2
// baseline (speedup 1.0000x reference)
#include <cuda_runtime.h>
#include <cuda_fp16.h>
#include <cstdint>
#include <cstddef>

// Problem constants
#define NB  256   // batch
#define SL  64    // seq len
#define NH  64    // heads
#define HD  64    // head dim
#define EMB 4096  // embed
#define LOG2E_O8 0.1803368801111204f   // log2(e)/8  (softmax scale 1/sqrt(64))
#define WSCALE    256.0f
#define INV_WSCALE 0.00390625f

// ---------------- scratch (device globals; no allocations allowed) ----------
__device__ __half g_wh[(size_t)EMB * EMB];            // 32 MB  fp16(w_out * 256)
__device__ __half g_vsumT[NB * HD * SL];              // 2 MB   [n][d][l]
__device__ float  g_E[(size_t)NB * SL * NH * NH];     // 268 MB [n][l][a][b]
__device__ float  g_zinv[SL * NH * NH];               // 1 MB   [l][a][b]
__device__ __half g_X[(size_t)NB * NH * EMB];         // 134 MB rows r=b*256+n

// ---------------- mma helpers ----------------
__device__ __forceinline__ void ldm_x4(uint32_t* r, const __half* p) {
    uint32_t a = (uint32_t)__cvta_generic_to_shared(p);
    asm volatile("ldmatrix.sync.aligned.m8n8.x4.shared.b16 {%0,%1,%2,%3}, [%4];"
                 : "=r"(r[0]), "=r"(r[1]), "=r"(r[2]), "=r"(r[3]) : "r"(a));
}

__device__ __forceinline__ void mma16816(float* c, const uint32_t* a, uint32_t b0, uint32_t b1) {
    asm volatile(
        "mma.sync.aligned.m16n8k16.row.col.f32.f16.f16.f32 "
        "{%0,%1,%2,%3}, {%4,%5,%6,%7}, {%8,%9}, {%0,%1,%2,%3};"
        : "+f"(c[0]), "+f"(c[1]), "+f"(c[2]), "+f"(c[3])
        : "r"(a[0]), "r"(a[1]), "r"(a[2]), "r"(a[3]), "r"(b0), "r"(b1));
}

// 64x64x64 GEMM core: 4 warps (128 thr), warp w computes rows [16w,16w+16).
// sA: (m,k) row-major, stride 72 halves. sB: (n,k) row-major, stride 72 halves.
__device__ __forceinline__ void gemm64_core(const __half* sA, const __half* sB, float acc[8][4]) {
    int w = threadIdx.x >> 5, lane = threadIdx.x & 31;
    int lr = lane & 15, lc = lane >> 4;
#pragma unroll
    for (int kt = 0; kt < 4; kt++) {
        uint32_t af[4];
        ldm_x4(af, &sA[(w * 16 + lr) * 72 + kt * 16 + lc * 8]);
#pragma unroll
        for (int bp = 0; bp < 4; bp++) {
            uint32_t bf[4];
            ldm_x4(bf, &sB[(bp * 16 + lr) * 72 + kt * 16 + lc * 8]);
            mma16816(acc[bp * 2],     af, bf[0], bf[2]);
            mma16816(acc[bp * 2 + 1], af, bf[1], bf[3]);
        }
    }
}

// ---------------- K0: convert weights to fp16 (scaled) ----------------
__global__ void __launch_bounds__(1024) k_convw(const float* __restrict__ w) {
    size_t i = (size_t)blockIdx.x * 1024 + threadIdx.x;  // 4.19M threads, 4 elems each
    float4 v = ((const float4*)w)[i];
    __half2* o = (__half2*)g_wh;
    o[i * 2]     = __floats2half2_rn(v.x * WSCALE, v.y * WSCALE);
    o[i * 2 + 1] = __floats2half2_rn(v.z * WSCALE, v.w * WSCALE);
}

// ---------------- K1: Vsum over value heads, stored transposed [n][d][l] ----
__global__ void __launch_bounds__(1024) k_vsum(const float* __restrict__ values) {
    int t = blockIdx.x * 1024 + threadIdx.x;          // NB*SL*HD = 1M
    int d = t & 63, l = (t >> 6) & 63, n = t >> 12;
    const float* p = values + ((size_t)(n * 64 + l)) * EMB + d;
    float s = 0.f;
#pragma unroll
    for (int v = 0; v < 64; v++) s += p[v * 64];
    g_vsumT[(n * 64 + d) * 64 + l] = __float2half_rn(s);
}

// ---------------- K2: energy E[n][l][a][b] = Q_head_a . K_head_b ------------
__global__ void __launch_bounds__(128) k_energy(const float* __restrict__ q,
                                                const float* __restrict__ kk) {
    __shared__ __half sA[64 * 72];
    __shared__ __half sB[64 * 72];
    int nl = blockIdx.x;                               // n*64 + l
    const float* qr = q  + (size_t)nl * EMB;
    const float* kr = kk + (size_t)nl * EMB;
    for (int i = threadIdx.x; i < 4096; i += 128) {
        int r = i >> 6, c = i & 63;
        sA[r * 72 + c] = __float2half_rn(qr[i]);
        sB[r * 72 + c] = __float2half_rn(kr[i]);
    }
    __syncthreads();

    float acc[8][4];
#pragma unroll
    for (int i = 0; i < 8; i++) acc[i][0] = acc[i][1] = acc[i][2] = acc[i][3] = 0.f;
    gemm64_core(sA, sB, acc);

    float* eo = g_E + (size_t)nl * 4096;
    int lane = threadIdx.x & 31, w = threadIdx.x >> 5;
    int r0 = w * 16 + (lane >> 2);
    int c0 = (lane & 3) * 2;
#pragma unroll
    for (int nt = 0; nt < 8; nt++) {
        int col = nt * 8 + c0;
        eo[r0 * 64 + col]           = acc[nt][0];
        eo[r0 * 64 + col + 1]       = acc[nt][1];
        eo[(r0 + 8) * 64 + col]     = acc[nt][2];
        eo[(r0 + 8) * 64 + col + 1] = acc[nt][3];
    }
}

// ---------------- K3: softmax denominator over batch axis -------------------
// zinv[l][a][b] = 1 / sum_n mask[n,l] * exp(E[n][l][a][b]/8)
__global__ void __launch_bounds__(256) k_zsum(const int* __restrict__ mask) {
    int c = blockIdx.x * 256 + threadIdx.x;   // c = l*4096 + a*64 + b, 262144 total
    int l = c >> 12;
    const float* ep = g_E + c;
    float z = 0.f;
#pragma unroll 4
    for (int n = 0; n < NB; n++) {
        if (mask[(n << 6) + l])
            z += exp2f(ep[(size_t)n * (SL * NH * NH)] * LOG2E_O8);
    }
    g_zinv[c] = (z > 0.f) ? (1.f / z) : 0.f;
}

// ---------------- K4: X[r=b*256+n, q*64+d] = sum_l att[q,b,n,l]*Vsum[n,l,d] -
__global__ void __launch_bounds__(128) k_attv(const int* __restrict__ mask) {
    __shared__ __half sA[64 * 72];   // att'[b][l]
    __shared__ __half sB[64 * 72];   // VsumT[d][l]
    int n  = blockIdx.x >> 6;
    int qh = blockIdx.x & 63;

    for (int i = threadIdx.x; i < 4096; i += 128) {
        int r = i >> 6, c = i & 63;
        sB[r * 72 + c] = g_vsumT[n * 4096 + i];
    }
    for (int i = threadIdx.x; i < 4096; i += 128) {
        int l = i >> 6, b = i & 63;
        float e = g_E[((size_t)(n * 64 + l)) * 4096 + qh * 64 + b];
        float att = 0.f;
        if (mask[n * 64 + l])
            att = exp2f(e * LOG2E_O8) * g_zinv[(l * 64 + qh) * 64 + b];
        sA[b * 72 + l] = __float2half_rn(att);
    }
    __syncthreads();

    float acc[8][4];
#pragma unroll
    for (int i = 0; i < 8; i++) acc[i][0] = acc[i][1] = acc[i][2] = acc[i][3] = 0.f;
    gemm64_core(sA, sB, acc);

    int lane = threadIdx.x & 31, w = threadIdx.x >> 5;
    int r0 = w * 16 + (lane >> 2);   // b row
    int c0 = (lane & 3) * 2;
#pragma unroll
    for (int nt = 0; nt < 8; nt++) {
        int col = qh * 64 + nt * 8 + c0;
        size_t o0 = ((size_t)(r0 * 256 + n)) * EMB + col;
        *(__half2*)(g_X + o0) = __floats2half2_rn(acc[nt][0], acc[nt][1]);
        size_t o1 = ((size_t)((r0 + 8) * 256 + n)) * EMB + col;
        *(__half2*)(g_X + o1) = __floats2half2_rn(acc[nt][2], acc[nt][3]);
    }
}

// ---------------- K5: out = X @ W^T / 256 + bias  (16384 x 4096 x 4096) -----
#define BM 128
#define BN 128
#define BK 32
#define SST 40   // smem stride in halves (padded)

__global__ void __launch_bounds__(256) k_gemm(const float* __restrict__ bias,
                                              float* __restrict__ out) {
    __shared__ __half sA[2][BM * SST];
    __shared__ __half sB[2][BN * SST];
    int bn = blockIdx.x, bm = blockIdx.y;
    int tid = threadIdx.x;
    const __half* gA = g_X  + (size_t)(bm * BM) * EMB;
    const __half* gB = g_wh + (size_t)(bn * BN) * EMB;

    auto load_stage = [&](int kt, int buf) {
#pragma unroll
        for (int i = 0; i < 2; i++) {
            int ch  = tid + i * 256;          // 512 chunks of 16B per operand
            int row = ch >> 2, c8 = (ch & 3) * 8;
            uint32_t sa = (uint32_t)__cvta_generic_to_shared(&sA[buf][row * SST + c8]);
            const __half* ga = gA + (size_t)row * EMB + kt * BK + c8;
            asm volatile("cp.async.cg.shared.global [%0], [%1], 16;\n" :: "r"(sa), "l"(ga));
            uint32_t sb = (uint32_t)__cvta_generic_to_shared(&sB[buf][row * SST + c8]);
            const __half* gb = gB + (size_t)row * EMB + kt * BK + c8;
            asm volatile("cp.async.cg.shared.global [%0], [%1], 16;\n" :: "r"(sb), "l"(gb));
        }
        asm volatile("cp.async.commit_group;\n");
    };

    int w = tid >> 5, lane = tid & 31;
    int wm = (w & 1) * 64, wn = (w >> 1) * 32;
    int lr = lane & 15, lc = lane >> 4;

    float acc[4][4][4];
#pragma unroll
    for (int m = 0; m < 4; m++)
#pragma unroll
        for (int nn = 0; nn < 4; nn++)
            acc[m][nn][0] = acc[m][nn][1] = acc[m][nn][2] = acc[m][nn][3] = 0.f;

    const int KT = EMB / BK;  // 128
    load_stage(0, 0);
    for (int kt = 0; kt < KT; kt++) {
        int buf = kt & 1;
        if (kt + 1 < KT) {
            load_stage(kt + 1, buf ^ 1);
            asm volatile("cp.async.wait_group 1;\n");
        } else {
            asm volatile("cp.async.wait_group 0;\n");
        }
        __syncthreads();
#pragma unroll
        for (int ks = 0; ks < 2; ks++) {
            uint32_t af[4][4];
#pragma unroll
            for (int mt = 0; mt < 4; mt++)
                ldm_x4(af[mt], &sA[buf][(wm + mt * 16 + lr) * SST + ks * 16 + lc * 8]);
#pragma unroll
            for (int bp = 0; bp < 2; bp++) {
                uint32_t bf[4];
                ldm_x4(bf, &sB[buf][(wn + bp * 16 + lr) * SST + ks * 16 + lc * 8]);
#pragma unroll
                for (int mt = 0; mt < 4; mt++) {
                    mma16816(acc[mt][bp * 2],     af[mt], bf[0], bf[2]);
                    mma16816(acc[mt][bp * 2 + 1], af[mt], bf[1], bf[3]);
                }
            }
        }
        __syncthreads();
    }

    int r = lane >> 2, c = (lane & 3) * 2;
#pragma unroll
    for (int mt = 0; mt < 4; mt++) {
        int row0 = bm * BM + wm + mt * 16 + r;
#pragma unroll
        for (int nt = 0; nt < 4; nt++) {
            int col = bn * BN + wn + nt * 8 + c;
            float b0 = bias[col], b1 = bias[col + 1];
            size_t o0 = (size_t)row0 * EMB + col;
            out[o0]     = acc[mt][nt][0] * INV_WSCALE + b0;
            out[o0 + 1] = acc[mt][nt][1] * INV_WSCALE + b1;
            size_t o1 = (size_t)(row0 + 8) * EMB + col;
            out[o1]     = acc[mt][nt][2] * INV_WSCALE + b0;
            out[o1 + 1] = acc[mt][nt][3] * INV_WSCALE + b1;
        }
    }
}

// ---------------- launch ----------------
extern "C" void kernel_launch(void* const* d_in, const int* in_sizes, int n_in,
                              void* d_out, int out_size) {
    const float* values = (const float*)d_in[0];
    const float* keys   = (const float*)d_in[1];
    const float* query  = (const float*)d_in[2];
    const int*   mask   = (const int*)d_in[3];
    const float* w_out  = (const float*)d_in[4];
    const float* b_out  = (const float*)d_in[5];
    float* out = (float*)d_out;

    k_convw<<<4096, 1024>>>(w_out);                 // 16.7M weights
    k_vsum<<<1024, 1024>>>(values);                 // 1M outputs
    k_energy<<<NB * SL, 128>>>(query, keys);        // 16384 blocks
    k_zsum<<<(SL * NH * NH) / 256, 256>>>(mask);    // 1024 blocks
    k_attv<<<NB * NH, 128>>>(mask);                 // 16384 blocks
    dim3 g5(EMB / BN, (NB * NH) / BM);              // (32, 128)
    k_gemm<<<g5, 256>>>(b_out, out);
}

// round 4
// speedup vs baseline: 1.0021x; 1.0021x over previous
#include <cuda_runtime.h>
#include <cuda_fp16.h>
#include <cstdint>
#include <cstddef>

// Problem constants
#define NB  256   // batch
#define SL  64    // seq len
#define NH  64    // heads
#define HD  64    // head dim
#define EMB 4096  // embed
#define LOG2E_O8 0.1803368801111204f   // log2(e)/8  (softmax scale 1/sqrt(64))
#define WSCALE    256.0f
#define INV_WSCALE 0.00390625f

// ---------------- scratch (device globals; no allocations allowed) ----------
__device__ __half g_wh[(size_t)EMB * EMB];            // 32 MB  fp16(w_out * 256)
__device__ __half g_vsumT[NB * HD * SL];              // 2 MB   [n][d][l]
__device__ float  g_E[(size_t)NB * SL * NH * NH];     // 268 MB [n][l][a][b]
__device__ float  g_zinv[SL * NH * NH];               // 1 MB   [l][a][b]
__device__ __half g_X[(size_t)NB * NH * EMB];         // 134 MB rows r=b*256+n

// ---------------- mma helpers ----------------
__device__ __forceinline__ void ldm_x4(uint32_t* r, const __half* p) {
    uint32_t a = (uint32_t)__cvta_generic_to_shared(p);
    asm volatile("ldmatrix.sync.aligned.m8n8.x4.shared.b16 {%0,%1,%2,%3}, [%4];"
                 : "=r"(r[0]), "=r"(r[1]), "=r"(r[2]), "=r"(r[3]) : "r"(a));
}

__device__ __forceinline__ void mma16816(float* c, const uint32_t* a, uint32_t b0, uint32_t b1) {
    asm volatile(
        "mma.sync.aligned.m16n8k16.row.col.f32.f16.f16.f32 "
        "{%0,%1,%2,%3}, {%4,%5,%6,%7}, {%8,%9}, {%0,%1,%2,%3};"
        : "+f"(c[0]), "+f"(c[1]), "+f"(c[2]), "+f"(c[3])
        : "r"(a[0]), "r"(a[1]), "r"(a[2]), "r"(a[3]), "r"(b0), "r"(b1));
}

// 64x64x64 GEMM core: 4 warps (128 thr), warp w computes rows [16w,16w+16).
// sA: (m,k) row-major, stride 72 halves. sB: (n,k) row-major, stride 72 halves.
__device__ __forceinline__ void gemm64_core(const __half* sA, const __half* sB, float acc[8][4]) {
    int w = threadIdx.x >> 5, lane = threadIdx.x & 31;
    int lr = lane & 15, lc = lane >> 4;
#pragma unroll
    for (int kt = 0; kt < 4; kt++) {
        uint32_t af[4];
        ldm_x4(af, &sA[(w * 16 + lr) * 72 + kt * 16 + lc * 8]);
#pragma unroll
        for (int bp = 0; bp < 4; bp++) {
            uint32_t bf[4];
            ldm_x4(bf, &sB[(bp * 16 + lr) * 72 + kt * 16 + lc * 8]);
            mma16816(acc[bp * 2],     af, bf[0], bf[2]);
            mma16816(acc[bp * 2 + 1], af, bf[1], bf[3]);
        }
    }
}

// ---------------- K0: convert weights to fp16 (scaled) ----------------
__global__ void __launch_bounds__(1024) k_convw(const float* __restrict__ w) {
    size_t i = (size_t)blockIdx.x * 1024 + threadIdx.x;  // 4.19M threads, 4 elems each
    float4 v = ((const float4*)w)[i];
    __half2* o = (__half2*)g_wh;
    o[i * 2]     = __floats2half2_rn(v.x * WSCALE, v.y * WSCALE);
    o[i * 2 + 1] = __floats2half2_rn(v.z * WSCALE, v.w * WSCALE);
}

// ---------------- K1: Vsum over value heads, stored transposed [n][d][l] ----
__global__ void __launch_bounds__(1024) k_vsum(const float* __restrict__ values) {
    int t = blockIdx.x * 1024 + threadIdx.x;          // NB*SL*HD = 1M
    int d = t & 63, l = (t >> 6) & 63, n = t >> 12;
    const float* p = values + ((size_t)(n * 64 + l)) * EMB + d;
    float s = 0.f;
#pragma unroll
    for (int v = 0; v < 64; v++) s += p[v * 64];
    g_vsumT[(n * 64 + d) * 64 + l] = __float2half_rn(s);
}

// ---------------- K2: energy E[n][l][a][b] = Q_head_a . K_head_b ------------
__global__ void __launch_bounds__(128) k_energy(const float* __restrict__ q,
                                                const float* __restrict__ kk) {
    __shared__ __half sA[64 * 72];
    __shared__ __half sB[64 * 72];
    int nl = blockIdx.x;                               // n*64 + l
    const float* qr = q  + (size_t)nl * EMB;
    const float* kr = kk + (size_t)nl * EMB;
    for (int i = threadIdx.x; i < 4096; i += 128) {
        int r = i >> 6, c = i & 63;
        sA[r * 72 + c] = __float2half_rn(qr[i]);
        sB[r * 72 + c] = __float2half_rn(kr[i]);
    }
    __syncthreads();

    float acc[8][4];
#pragma unroll
    for (int i = 0; i < 8; i++) acc[i][0] = acc[i][1] = acc[i][2] = acc[i][3] = 0.f;
    gemm64_core(sA, sB, acc);

    float* eo = g_E + (size_t)nl * 4096;
    int lane = threadIdx.x & 31, w = threadIdx.x >> 5;
    int r0 = w * 16 + (lane >> 2);
    int c0 = (lane & 3) * 2;
#pragma unroll
    for (int nt = 0; nt < 8; nt++) {
        int col = nt * 8 + c0;
        eo[r0 * 64 + col]           = acc[nt][0];
        eo[r0 * 64 + col + 1]       = acc[nt][1];
        eo[(r0 + 8) * 64 + col]     = acc[nt][2];
        eo[(r0 + 8) * 64 + col + 1] = acc[nt][3];
    }
}

// ---------------- K3: softmax denominator over batch axis -------------------
// zinv[l][a][b] = 1 / sum_n mask[n,l] * exp(E[n][l][a][b]/8)
__global__ void __launch_bounds__(256) k_zsum(const int* __restrict__ mask) {
    int c = blockIdx.x * 256 + threadIdx.x;   // c = l*4096 + a*64 + b, 262144 total
    int l = c >> 12;
    const float* ep = g_E + c;
    float z = 0.f;
#pragma unroll 4
    for (int n = 0; n < NB; n++) {
        if (mask[(n << 6) + l])
            z += exp2f(ep[(size_t)n * (SL * NH * NH)] * LOG2E_O8);
    }
    g_zinv[c] = (z > 0.f) ? (1.f / z) : 0.f;
}

// ---------------- K4: X[r=b*256+n, q*64+d] = sum_l att[q,b,n,l]*Vsum[n,l,d] -
__global__ void __launch_bounds__(128) k_attv(const int* __restrict__ mask) {
    __shared__ __half sA[64 * 72];   // att'[b][l]
    __shared__ __half sB[64 * 72];   // VsumT[d][l]
    int n  = blockIdx.x >> 6;
    int qh = blockIdx.x & 63;

    for (int i = threadIdx.x; i < 4096; i += 128) {
        int r = i >> 6, c = i & 63;
        sB[r * 72 + c] = g_vsumT[n * 4096 + i];
    }
    for (int i = threadIdx.x; i < 4096; i += 128) {
        int l = i >> 6, b = i & 63;
        float e = g_E[((size_t)(n * 64 + l)) * 4096 + qh * 64 + b];
        float att = 0.f;
        if (mask[n * 64 + l])
            att = exp2f(e * LOG2E_O8) * g_zinv[(l * 64 + qh) * 64 + b];
        sA[b * 72 + l] = __float2half_rn(att);
    }
    __syncthreads();

    float acc[8][4];
#pragma unroll
    for (int i = 0; i < 8; i++) acc[i][0] = acc[i][1] = acc[i][2] = acc[i][3] = 0.f;
    gemm64_core(sA, sB, acc);

    int lane = threadIdx.x & 31, w = threadIdx.x >> 5;
    int r0 = w * 16 + (lane >> 2);   // b row
    int c0 = (lane & 3) * 2;
#pragma unroll
    for (int nt = 0; nt < 8; nt++) {
        int col = qh * 64 + nt * 8 + c0;
        size_t o0 = ((size_t)(r0 * 256 + n)) * EMB + col;
        *(__half2*)(g_X + o0) = __floats2half2_rn(acc[nt][0], acc[nt][1]);
        size_t o1 = ((size_t)((r0 + 8) * 256 + n)) * EMB + col;
        *(__half2*)(g_X + o1) = __floats2half2_rn(acc[nt][2], acc[nt][3]);
    }
}

// ---------------- K5: out = X @ W^T / 256 + bias  (16384 x 4096 x 4096) -----
#define BM 128
#define BN 128
#define BK 32
#define SST 40   // smem stride in halves (padded)

__global__ void __launch_bounds__(256) k_gemm(const float* __restrict__ bias,
                                              float* __restrict__ out) {
    __shared__ __half sA[2][BM * SST];
    __shared__ __half sB[2][BN * SST];
    int bn = blockIdx.x, bm = blockIdx.y;
    int tid = threadIdx.x;
    const __half* gA = g_X  + (size_t)(bm * BM) * EMB;
    const __half* gB = g_wh + (size_t)(bn * BN) * EMB;

    auto load_stage = [&](int kt, int buf) {
#pragma unroll
        for (int i = 0; i < 2; i++) {
            int ch  = tid + i * 256;          // 512 chunks of 16B per operand
            int row = ch >> 2, c8 = (ch & 3) * 8;
            uint32_t sa = (uint32_t)__cvta_generic_to_shared(&sA[buf][row * SST + c8]);
            const __half* ga = gA + (size_t)row * EMB + kt * BK + c8;
            asm volatile("cp.async.cg.shared.global [%0], [%1], 16;\n" :: "r"(sa), "l"(ga));
            uint32_t sb = (uint32_t)__cvta_generic_to_shared(&sB[buf][row * SST + c8]);
            const __half* gb = gB + (size_t)row * EMB + kt * BK + c8;
            asm volatile("cp.async.cg.shared.global [%0], [%1], 16;\n" :: "r"(sb), "l"(gb));
        }
        asm volatile("cp.async.commit_group;\n");
    };

    int w = tid >> 5, lane = tid & 31;
    int wm = (w & 1) * 64, wn = (w >> 1) * 32;
    int lr = lane & 15, lc = lane >> 4;

    float acc[4][4][4];
#pragma unroll
    for (int m = 0; m < 4; m++)
#pragma unroll
        for (int nn = 0; nn < 4; nn++)
            acc[m][nn][0] = acc[m][nn][1] = acc[m][nn][2] = acc[m][nn][3] = 0.f;

    const int KT = EMB / BK;  // 128
    load_stage(0, 0);
    for (int kt = 0; kt < KT; kt++) {
        int buf = kt & 1;
        if (kt + 1 < KT) {
            load_stage(kt + 1, buf ^ 1);
            asm volatile("cp.async.wait_group 1;\n");
        } else {
            asm volatile("cp.async.wait_group 0;\n");
        }
        __syncthreads();
#pragma unroll
        for (int ks = 0; ks < 2; ks++) {
            uint32_t af[4][4];
#pragma unroll
            for (int mt = 0; mt < 4; mt++)
                ldm_x4(af[mt], &sA[buf][(wm + mt * 16 + lr) * SST + ks * 16 + lc * 8]);
#pragma unroll
            for (int bp = 0; bp < 2; bp++) {
                uint32_t bf[4];
                ldm_x4(bf, &sB[buf][(wn + bp * 16 + lr) * SST + ks * 16 + lc * 8]);
#pragma unroll
                for (int mt = 0; mt < 4; mt++) {
                    mma16816(acc[mt][bp * 2],     af[mt], bf[0], bf[2]);
                    mma16816(acc[mt][bp * 2 + 1], af[mt], bf[1], bf[3]);
                }
            }
        }
        __syncthreads();
    }

    int r = lane >> 2, c = (lane & 3) * 2;
#pragma unroll
    for (int mt = 0; mt < 4; mt++) {
        int row0 = bm * BM + wm + mt * 16 + r;
#pragma unroll
        for (int nt = 0; nt < 4; nt++) {
            int col = bn * BN + wn + nt * 8 + c;
            float b0 = bias[col], b1 = bias[col + 1];
            size_t o0 = (size_t)row0 * EMB + col;
            out[o0]     = acc[mt][nt][0] * INV_WSCALE + b0;
            out[o0 + 1] = acc[mt][nt][1] * INV_WSCALE + b1;
            size_t o1 = (size_t)(row0 + 8) * EMB + col;
            out[o1]     = acc[mt][nt][2] * INV_WSCALE + b0;
            out[o1 + 1] = acc[mt][nt][3] * INV_WSCALE + b1;
        }
    }
}

// ---------------- launch ----------------
extern "C" void kernel_launch(void* const* d_in, const int* in_sizes, int n_in,
                              void* d_out, int out_size) {
    const float* values = (const float*)d_in[0];
    const float* keys   = (const float*)d_in[1];
    const float* query  = (const float*)d_in[2];
    const int*   mask   = (const int*)d_in[3];
    const float* w_out  = (const float*)d_in[4];
    const float* b_out  = (const float*)d_in[5];
    float* out = (float*)d_out;

    k_convw<<<4096, 1024>>>(w_out);                 // 16.7M weights
    k_vsum<<<1024, 1024>>>(values);                 // 1M outputs
    k_energy<<<NB * SL, 128>>>(query, keys);        // 16384 blocks
    k_zsum<<<(SL * NH * NH) / 256, 256>>>(mask);    // 1024 blocks
    k_attv<<<NB * NH, 128>>>(mask);                 // 16384 blocks
    dim3 g5(EMB / BN, (NB * NH) / BM);              // (32, 128)
    k_gemm<<<g5, 256>>>(b_out, out);
}